// round 9
// baseline (speedup 1.0000x reference)
#include <cuda_runtime.h>

#define B_ 128
#define T_ 1024
#define I_ 128
#define H_ 256
#define O_ 64

// Scratch (device globals — no allocations allowed)
__device__ float g_xw[(size_t)B_ * T_ * H_];  // 128 MB: x @ W_xh^T + b_h
__device__ float g_hs[(size_t)B_ * T_ * H_];  // 128 MB: hidden states

// ---------------------------------------------------------------------------
// Packed f32x2 helpers (sm_103a FFMA2 path)
// ---------------------------------------------------------------------------
__device__ __forceinline__ void ffma2(unsigned long long &acc,
                                      unsigned long long a,
                                      unsigned long long b) {
    asm("fma.rn.f32x2 %0, %1, %2, %0;" : "+l"(acc) : "l"(a), "l"(b));
}
__device__ __forceinline__ unsigned long long dup2(float a) {
    unsigned long long r;
    asm("mov.b64 %0, {%1, %1};" : "=l"(r) : "f"(a));
    return r;
}
__device__ __forceinline__ float2 unpack2(unsigned long long v) {
    float2 r;
    asm("mov.b64 {%0, %1}, %2;" : "=f"(r.x), "=f"(r.y) : "l"(v));
    return r;
}

// ---------------------------------------------------------------------------
// Phase 1: g_xw[row,h] = sum_i x[row,i] * W_xh[h,i] + b_h[h]
// NT GEMM: M=131072 rows, N=256, K=128. Tile 128x128, 256 threads,
// thread computes 8 rows x 4 f32x2-col-pairs.  (known-good, 213us)
// ---------------------------------------------------------------------------
#define P1_PAD 132
#define P1_SMEM ((128 * P1_PAD + 128 * P1_PAD) * 4)

__global__ __launch_bounds__(256, 1) void p1_kernel(
    const float* __restrict__ x, const float* __restrict__ Wxh,
    const float* __restrict__ bh) {
    extern __shared__ float sm[];
    float* As  = sm;                  // [128 m][P1_PAD] (m x k)
    float* BsT = sm + 128 * P1_PAD;   // [128 k][P1_PAD] (k x n)
    const int tid = threadIdx.x;
    const int mt = blockIdx.x >> 1;
    const int nt = blockIdx.x & 1;

    const float* Ag = x + (size_t)mt * 128 * I_;
#pragma unroll
    for (int i = 0; i < 16; i++) {
        int lin = tid + 256 * i;
        int r = lin >> 5, c4 = lin & 31;
        float4 v = ((const float4*)Ag)[r * 32 + c4];
        *(float4*)(As + r * P1_PAD + c4 * 4) = v;
    }
    {
        int n = tid & 127, kg = tid >> 7;
        const float4* Bg = (const float4*)(Wxh + (size_t)(nt * 128 + n) * I_ + kg * 64);
#pragma unroll
        for (int q = 0; q < 16; q++) {
            float4 v = Bg[q];
            int kb = kg * 64 + q * 4;
            BsT[(kb + 0) * P1_PAD + n] = v.x;
            BsT[(kb + 1) * P1_PAD + n] = v.y;
            BsT[(kb + 2) * P1_PAD + n] = v.z;
            BsT[(kb + 3) * P1_PAD + n] = v.w;
        }
    }
    __syncthreads();

    const int tx = tid & 15, ty = tid >> 4;
    unsigned long long acc[8][4];
#pragma unroll
    for (int u = 0; u < 8; u++)
#pragma unroll
        for (int v = 0; v < 4; v++) acc[u][v] = 0ull;

#pragma unroll 4
    for (int k = 0; k < 128; k++) {
        unsigned long long a2[8], b2[4];
#pragma unroll
        for (int u = 0; u < 8; u++)
            a2[u] = dup2(As[(ty + 16 * u) * P1_PAD + k]);
#pragma unroll
        for (int v = 0; v < 4; v++)
            b2[v] = *(const unsigned long long*)(BsT + k * P1_PAD + 2 * tx + 32 * v);
#pragma unroll
        for (int u = 0; u < 8; u++)
#pragma unroll
            for (int v = 0; v < 4; v++) ffma2(acc[u][v], a2[u], b2[v]);
    }

    float2 bias[4];
#pragma unroll
    for (int v = 0; v < 4; v++)
        bias[v] = *(const float2*)(bh + nt * 128 + 2 * tx + 32 * v);
#pragma unroll
    for (int u = 0; u < 8; u++) {
        size_t row = (size_t)mt * 128 + ty + 16 * u;
        float* op = g_xw + row * H_ + nt * 128;
#pragma unroll
        for (int v = 0; v < 4; v++) {
            float2 r = unpack2(acc[u][v]);
            r.x += bias[v].x;
            r.y += bias[v].y;
            *(float2*)(op + 2 * tx + 32 * v) = r;
        }
    }
}

// ---------------------------------------------------------------------------
// Phase 2: sequential scan. 1 CTA per batch (128 CTAs), 256 threads.
// Thread h computes h_new[h]. W_hh row h: k in [0,208) in registers
// (104 packed u64), k in [208,256) in smem as ulonglong2 [j2][h]
// (12 LDS.128/thread/step, conflict-free). h double-buffered in smem;
// 4-deep xW register FIFO; software-pipelined h loads; 4 acc chains.
// ---------------------------------------------------------------------------
#define NJR 104  // u64 W pairs in registers per thread (k = 0..207)
#define NJ2 12   // ulonglong2 W chunks in smem per h   (k = 208..255)
#define RNN_SMEM (NJ2 * H_ * 16 + 2 * H_ * 4)
#define XF 4     // xW prefetch FIFO depth

__global__ __launch_bounds__(256, 1) void rnn_kernel(
    const float* __restrict__ Whh) {
    extern __shared__ char smraw[];
    ulonglong2* Wsm2 = (ulonglong2*)smraw;              // [NJ2][H_]
    float* hb = (float*)(smraw + NJ2 * H_ * 16);        // [2][H_]
    const int h = threadIdx.x;
    const int b = blockIdx.x;

    const unsigned long long* wrow =
        (const unsigned long long*)(Whh + (size_t)h * H_);
    unsigned long long wreg[NJR];
#pragma unroll
    for (int j = 0; j < NJR; j++) wreg[j] = wrow[j];
#pragma unroll
    for (int j2 = 0; j2 < NJ2; j2++) {
        ulonglong2 wv;
        wv.x = wrow[NJR + 2 * j2];
        wv.y = wrow[NJR + 2 * j2 + 1];
        Wsm2[j2 * H_ + h] = wv;
    }
    hb[h] = 0.0f;
    hb[H_ + h] = 0.0f;

    const float* xwp = g_xw + (size_t)b * T_ * H_ + h;
    float* hsp = g_hs + (size_t)b * T_ * H_ + h;

    float xwf[XF];
#pragma unroll
    for (int i = 0; i < XF; i++)
        xwf[i] = __ldg(xwp + (size_t)i * H_);
    __syncthreads();

    int cur = 0;
#pragma unroll 1
    for (int t = 0; t < T_; t++) {
        const ulonglong2* h2 = (const ulonglong2*)(hb + cur * H_);
        unsigned long long acc0 = 0ull, acc1 = 0ull, acc2 = 0ull, acc3 = 0ull;

        // software-pipelined: prefetch next iteration's h chunk before use
        ulonglong2 hv = h2[0];
        // register part: 52 iterations (k = 0..207)
#pragma unroll
        for (int j = 0; j < NJR / 2; j++) {
            ulonglong2 hvn = h2[j + 1];  // j+1 <= 52 < 64 total chunks: safe
            if (j & 1) {
                ffma2(acc2, hv.x, wreg[2 * j]);
                ffma2(acc3, hv.y, wreg[2 * j + 1]);
            } else {
                ffma2(acc0, hv.x, wreg[2 * j]);
                ffma2(acc1, hv.y, wreg[2 * j + 1]);
            }
            hv = hvn;
        }
        // smem part: 12 iterations (k = 208..255); hv holds chunk 52
#pragma unroll
        for (int j2 = 0; j2 < NJ2; j2++) {
            ulonglong2 hvn = (j2 < NJ2 - 1) ? h2[NJR / 2 + j2 + 1] : hv;
            ulonglong2 wv = Wsm2[j2 * H_ + h];
            if (j2 & 1) {
                ffma2(acc2, hv.x, wv.x);
                ffma2(acc3, hv.y, wv.y);
            } else {
                ffma2(acc0, hv.x, wv.x);
                ffma2(acc1, hv.y, wv.y);
            }
            hv = hvn;
        }

        float2 a0 = unpack2(acc0), a1 = unpack2(acc1);
        float2 a2 = unpack2(acc2), a3 = unpack2(acc3);
        float s = ((a0.x + a0.y) + (a1.x + a1.y)) +
                  ((a2.x + a2.y) + (a3.x + a3.y));
        float hnew = fmaxf(xwf[t & (XF - 1)] + s, 0.0f);
        hb[(cur ^ 1) * H_ + h] = hnew;
        hsp[(size_t)t * H_] = hnew;
        // refill FIFO slot: prefetch step t+XF (wrapped loads unused)
        xwf[t & (XF - 1)] = __ldg(xwp + (size_t)((t + XF) & (T_ - 1)) * H_);
        cur ^= 1;
        __syncthreads();
    }
}

// ---------------------------------------------------------------------------
// Phase 3: out[row,o] = sum_h g_hs[row,h] * W_out[o,h] + b_out[o]
// M=131072, N=64, K=256. Tile 128 rows x 64 cols.
// ---------------------------------------------------------------------------
#define P3_WPAD 66
#define P3_APAD 68
#define P3_SMEM ((256 * P3_WPAD + 128 * P3_APAD) * 4)

__global__ __launch_bounds__(256, 1) void p3_kernel(
    const float* __restrict__ Wout, const float* __restrict__ bout,
    float* __restrict__ out) {
    extern __shared__ float sm[];
    float* WsT = sm;                    // [256 k][P3_WPAD] (k x o)
    float* As  = sm + 256 * P3_WPAD;    // [128 m][P3_APAD] (m x k-chunk)
    const int tid = threadIdx.x;
    const int mt = blockIdx.x;

    {
        int o = tid >> 2, kq = tid & 3;
        const float4* Wg = (const float4*)(Wout + (size_t)o * H_ + kq * 64);
#pragma unroll
        for (int q = 0; q < 16; q++) {
            float4 v = Wg[q];
            int kb = kq * 64 + q * 4;
            WsT[(kb + 0) * P3_WPAD + o] = v.x;
            WsT[(kb + 1) * P3_WPAD + o] = v.y;
            WsT[(kb + 2) * P3_WPAD + o] = v.z;
            WsT[(kb + 3) * P3_WPAD + o] = v.w;
        }
    }

    const int tx = tid & 15, ty = tid >> 4;
    unsigned long long acc[8][2];
#pragma unroll
    for (int u = 0; u < 8; u++) { acc[u][0] = 0ull; acc[u][1] = 0ull; }

    for (int kc = 0; kc < 4; kc++) {
        __syncthreads();
#pragma unroll
        for (int i = 0; i < 8; i++) {
            int lin = tid + 256 * i;
            int r = lin >> 4, c4 = lin & 15;
            float4 v = *(const float4*)(g_hs + ((size_t)mt * 128 + r) * H_ +
                                        kc * 64 + c4 * 4);
            *(float4*)(As + r * P3_APAD + c4 * 4) = v;
        }
        __syncthreads();
#pragma unroll 4
        for (int k = 0; k < 64; k++) {
            unsigned long long b0 = *(const unsigned long long*)(
                WsT + (kc * 64 + k) * P3_WPAD + 2 * tx);
            unsigned long long b1 = *(const unsigned long long*)(
                WsT + (kc * 64 + k) * P3_WPAD + 2 * tx + 32);
#pragma unroll
            for (int u = 0; u < 8; u++) {
                unsigned long long a2 = dup2(As[(ty + 16 * u) * P3_APAD + k]);
                ffma2(acc[u][0], a2, b0);
                ffma2(acc[u][1], a2, b1);
            }
        }
    }

    float2 bias0 = *(const float2*)(bout + 2 * tx);
    float2 bias1 = *(const float2*)(bout + 2 * tx + 32);
#pragma unroll
    for (int u = 0; u < 8; u++) {
        size_t row = (size_t)mt * 128 + ty + 16 * u;
        float2 r0 = unpack2(acc[u][0]);
        float2 r1 = unpack2(acc[u][1]);
        r0.x += bias0.x; r0.y += bias0.y;
        r1.x += bias1.x; r1.y += bias1.y;
        *(float2*)(out + row * O_ + 2 * tx) = r0;
        *(float2*)(out + row * O_ + 2 * tx + 32) = r1;
    }
}

// ---------------------------------------------------------------------------
extern "C" void kernel_launch(void* const* d_in, const int* in_sizes, int n_in,
                              void* d_out, int out_size) {
    const float* x    = (const float*)d_in[0];
    const float* Wxh  = (const float*)d_in[1];
    const float* Whh  = (const float*)d_in[2];
    const float* bh   = (const float*)d_in[3];
    const float* Wout = (const float*)d_in[4];
    const float* bout = (const float*)d_in[5];
    float* out = (float*)d_out;

    cudaFuncSetAttribute(p1_kernel, cudaFuncAttributeMaxDynamicSharedMemorySize, P1_SMEM);
    cudaFuncSetAttribute(rnn_kernel, cudaFuncAttributeMaxDynamicSharedMemorySize, RNN_SMEM);
    cudaFuncSetAttribute(p3_kernel, cudaFuncAttributeMaxDynamicSharedMemorySize, P3_SMEM);

    p1_kernel<<<(B_ * T_ / 128) * 2, 256, P1_SMEM>>>(x, Wxh, bh);
    rnn_kernel<<<B_, 256, RNN_SMEM>>>(Whh);
    p3_kernel<<<B_ * T_ / 128, 256, P3_SMEM>>>(Wout, bout, out);
}

// round 11
// speedup vs baseline: 1.3361x; 1.3361x over previous
#include <cuda_runtime.h>

#define B_ 128
#define T_ 1024
#define I_ 128
#define H_ 256
#define O_ 64

// Scratch (device globals — no allocations allowed)
__device__ float g_xw[(size_t)B_ * T_ * H_];  // 128 MB: x @ W_xh^T + b_h
__device__ float g_hs[(size_t)B_ * T_ * H_];  // 128 MB: hidden states
__device__ float g_woT[H_ * O_];              // 64 KB: W_out transposed [k][o]

// ---------------------------------------------------------------------------
// Packed f32x2 helpers (sm_103a FFMA2 path)
// ---------------------------------------------------------------------------
__device__ __forceinline__ void ffma2(unsigned long long &acc,
                                      unsigned long long a,
                                      unsigned long long b) {
    asm("fma.rn.f32x2 %0, %1, %2, %0;" : "+l"(acc) : "l"(a), "l"(b));
}
__device__ __forceinline__ unsigned long long dup2(float a) {
    unsigned long long r;
    asm("mov.b64 %0, {%1, %1};" : "=l"(r) : "f"(a));
    return r;
}
__device__ __forceinline__ float2 unpack2(unsigned long long v) {
    float2 r;
    asm("mov.b64 {%0, %1}, %2;" : "=f"(r.x), "=f"(r.y) : "l"(v));
    return r;
}

// ---------------------------------------------------------------------------
// Phase 1: g_xw[row,h] = sum_i x[row,i] * W_xh[h,i] + b_h[h]
// NT GEMM: M=131072 rows, N=256, K=128. Tile 128x128, K chunked 2x64 so
// smem = 68.6KB -> 2 CTAs/SM (16 warps) for latency hiding.
// ---------------------------------------------------------------------------
#define P1_APAD 68
#define P1_BPAD 132
#define P1_SMEM ((128 * P1_APAD + 64 * P1_BPAD) * 4)

__global__ __launch_bounds__(256, 2) void p1_kernel(
    const float* __restrict__ x, const float* __restrict__ Wxh,
    const float* __restrict__ bh) {
    extern __shared__ float sm[];
    float* As  = sm;                  // [128 m][P1_APAD] (m x k-chunk)
    float* BsT = sm + 128 * P1_APAD;  // [64 k][P1_BPAD]  (k x n)
    const int tid = threadIdx.x;
    const int mt = blockIdx.x >> 1;
    const int nt = blockIdx.x & 1;
    const int tx = tid & 15, ty = tid >> 4;

    unsigned long long acc[8][4];
#pragma unroll
    for (int u = 0; u < 8; u++)
#pragma unroll
        for (int v = 0; v < 4; v++) acc[u][v] = 0ull;

    const int n = tid & 127, kh = tid >> 7;  // B-loader mapping

    for (int kc = 0; kc < 2; kc++) {
        if (kc) __syncthreads();
        // A chunk: 128 rows x 64 floats
        const float* Ag = x + (size_t)mt * 128 * I_ + kc * 64;
#pragma unroll
        for (int i = 0; i < 8; i++) {
            int lin = tid + 256 * i;
            int r = lin >> 4, c4 = lin & 15;
            float4 v = ((const float4*)(Ag + r * I_))[c4];
            *(float4*)(As + r * P1_APAD + c4 * 4) = v;
        }
        // B chunk transposed: BsT[k][n] = Wxh[nt*128+n][kc*64+k]
        {
            const float4* Bg = (const float4*)(Wxh + (size_t)(nt * 128 + n) * I_ +
                                               kc * 64 + kh * 32);
#pragma unroll
            for (int q = 0; q < 8; q++) {
                float4 v = Bg[q];
                int kb = kh * 32 + q * 4;
                BsT[(kb + 0) * P1_BPAD + n] = v.x;
                BsT[(kb + 1) * P1_BPAD + n] = v.y;
                BsT[(kb + 2) * P1_BPAD + n] = v.z;
                BsT[(kb + 3) * P1_BPAD + n] = v.w;
            }
        }
        __syncthreads();

#pragma unroll 2
        for (int k = 0; k < 64; k++) {
            unsigned long long a2[8], b2[4];
#pragma unroll
            for (int u = 0; u < 8; u++)
                a2[u] = dup2(As[(ty + 16 * u) * P1_APAD + k]);
#pragma unroll
            for (int v = 0; v < 4; v++)
                b2[v] = *(const unsigned long long*)(BsT + k * P1_BPAD + 2 * tx + 32 * v);
#pragma unroll
            for (int u = 0; u < 8; u++)
#pragma unroll
                for (int v = 0; v < 4; v++) ffma2(acc[u][v], a2[u], b2[v]);
        }
    }

    float2 bias[4];
#pragma unroll
    for (int v = 0; v < 4; v++)
        bias[v] = *(const float2*)(bh + nt * 128 + 2 * tx + 32 * v);
#pragma unroll
    for (int u = 0; u < 8; u++) {
        size_t row = (size_t)mt * 128 + ty + 16 * u;
        float* op = g_xw + row * H_ + nt * 128;
#pragma unroll
        for (int v = 0; v < 4; v++) {
            float2 r = unpack2(acc[u][v]);
            r.x += bias[v].x;
            r.y += bias[v].y;
            *(float2*)(op + 2 * tx + 32 * v) = r;
        }
    }
}

// ---------------------------------------------------------------------------
// Phase 2: sequential scan — R4 configuration verbatim (known-good ~945us).
// 1 CTA per batch, 256 threads. W row: k in [0,192) in regs (96 u64),
// k in [192,256) in smem LDS.64 [j][h]. 4-deep xW FIFO, pipelined h loads,
// 4 accumulator chains.
// ---------------------------------------------------------------------------
#define NJR 96
#define NJS 32
#define RNN_SMEM (NJS * H_ * 8 + 2 * H_ * 4)
#define XF 4

__global__ __launch_bounds__(256, 1) void rnn_kernel(
    const float* __restrict__ Whh) {
    extern __shared__ float sm[];
    unsigned long long* WsmU = (unsigned long long*)sm;   // [NJS][H_]
    float* hb = sm + NJS * H_ * 2;                        // [2][H_]
    const int h = threadIdx.x;
    const int b = blockIdx.x;

    const float* wrow = Whh + (size_t)h * H_;
    unsigned long long wreg[NJR];
#pragma unroll
    for (int j = 0; j < NJR; j++)
        wreg[j] = ((const unsigned long long*)wrow)[j];
#pragma unroll
    for (int j = 0; j < NJS; j++)
        WsmU[j * H_ + h] = ((const unsigned long long*)wrow)[NJR + j];
    hb[h] = 0.0f;
    hb[H_ + h] = 0.0f;

    const float* xwp = g_xw + (size_t)b * T_ * H_ + h;
    float* hsp = g_hs + (size_t)b * T_ * H_ + h;

    float xwf[XF];
#pragma unroll
    for (int i = 0; i < XF; i++)
        xwf[i] = __ldg(xwp + (size_t)i * H_);
    __syncthreads();

    int cur = 0;
#pragma unroll 1
    for (int t = 0; t < T_; t++) {
        const ulonglong2* h2 = (const ulonglong2*)(hb + cur * H_);
        unsigned long long acc0 = 0ull, acc1 = 0ull, acc2 = 0ull, acc3 = 0ull;

        ulonglong2 hv = h2[0];
#pragma unroll
        for (int j = 0; j < NJR / 2; j++) {
            ulonglong2 hvn = h2[j + 1];
            if (j & 1) {
                ffma2(acc2, hv.x, wreg[2 * j]);
                ffma2(acc3, hv.y, wreg[2 * j + 1]);
            } else {
                ffma2(acc0, hv.x, wreg[2 * j]);
                ffma2(acc1, hv.y, wreg[2 * j + 1]);
            }
            hv = hvn;
        }
#pragma unroll
        for (int j = 0; j < NJS / 2; j++) {
            ulonglong2 hvn = (j < NJS / 2 - 1) ? h2[NJR / 2 + j + 1] : hv;
            unsigned long long w0 = WsmU[(2 * j) * H_ + h];
            unsigned long long w1 = WsmU[(2 * j + 1) * H_ + h];
            if (j & 1) {
                ffma2(acc2, hv.x, w0);
                ffma2(acc3, hv.y, w1);
            } else {
                ffma2(acc0, hv.x, w0);
                ffma2(acc1, hv.y, w1);
            }
            hv = hvn;
        }

        float2 a0 = unpack2(acc0), a1 = unpack2(acc1);
        float2 a2 = unpack2(acc2), a3 = unpack2(acc3);
        float s = ((a0.x + a0.y) + (a1.x + a1.y)) +
                  ((a2.x + a2.y) + (a3.x + a3.y));
        float hnew = fmaxf(xwf[t & (XF - 1)] + s, 0.0f);
        hb[(cur ^ 1) * H_ + h] = hnew;
        hsp[(size_t)t * H_] = hnew;
        xwf[t & (XF - 1)] = __ldg(xwp + (size_t)((t + XF) & (T_ - 1)) * H_);
        cur ^= 1;
        __syncthreads();
    }
}

// ---------------------------------------------------------------------------
// Phase 3a: transpose W_out -> g_woT[k][o]  (tiny, runs once)
// ---------------------------------------------------------------------------
__global__ void p3t_kernel(const float* __restrict__ Wout) {
    int i = threadIdx.x + blockIdx.x * 256;  // 16384 elems
    int o = i >> 8, k = i & 255;
    g_woT[k * O_ + o] = Wout[i];
}

// ---------------------------------------------------------------------------
// Phase 3b: out[row,o] = sum_h g_hs[row,h] * g_woT[h,o] + b_out[o]
// M=131072, N=64, K=256. A staged in 18KB smem chunks (32 k), W read via
// vectorized LDG (L1/L2-resident 64KB) -> 3 CTAs/SM.
// ---------------------------------------------------------------------------
#define P3_APAD 36
#define P3_SMEM (128 * P3_APAD * 4)

__global__ __launch_bounds__(256, 3) void p3_kernel(
    const float* __restrict__ bout, float* __restrict__ out) {
    extern __shared__ float sm[];
    float* As = sm;  // [128 m][P3_APAD]
    const int tid = threadIdx.x;
    const int mt = blockIdx.x;
    const int tx = tid & 15, ty = tid >> 4;

    unsigned long long acc[8][2];
#pragma unroll
    for (int u = 0; u < 8; u++) { acc[u][0] = 0ull; acc[u][1] = 0ull; }

    for (int kc = 0; kc < 8; kc++) {
        if (kc) __syncthreads();
        // stage 128 x 32 chunk of g_hs
#pragma unroll
        for (int i = 0; i < 4; i++) {
            int lin = tid + 256 * i;
            int r = lin >> 3, c4 = lin & 7;
            float4 v = *(const float4*)(g_hs + ((size_t)mt * 128 + r) * H_ +
                                        kc * 32 + c4 * 4);
            *(float4*)(As + r * P3_APAD + c4 * 4) = v;
        }
        __syncthreads();
#pragma unroll 4
        for (int k = 0; k < 32; k++) {
            int kk = kc * 32 + k;
            unsigned long long b0 = __ldg((const unsigned long long*)(
                g_woT + kk * O_ + 2 * tx));
            unsigned long long b1 = __ldg((const unsigned long long*)(
                g_woT + kk * O_ + 2 * tx + 32));
#pragma unroll
            for (int u = 0; u < 8; u++) {
                unsigned long long a2 = dup2(As[(ty + 16 * u) * P3_APAD + k]);
                ffma2(acc[u][0], a2, b0);
                ffma2(acc[u][1], a2, b1);
            }
        }
    }

    float2 bias0 = *(const float2*)(bout + 2 * tx);
    float2 bias1 = *(const float2*)(bout + 2 * tx + 32);
#pragma unroll
    for (int u = 0; u < 8; u++) {
        size_t row = (size_t)mt * 128 + ty + 16 * u;
        float2 r0 = unpack2(acc[u][0]);
        float2 r1 = unpack2(acc[u][1]);
        r0.x += bias0.x; r0.y += bias0.y;
        r1.x += bias1.x; r1.y += bias1.y;
        *(float2*)(out + row * O_ + 2 * tx) = r0;
        *(float2*)(out + row * O_ + 2 * tx + 32) = r1;
    }
}

// ---------------------------------------------------------------------------
extern "C" void kernel_launch(void* const* d_in, const int* in_sizes, int n_in,
                              void* d_out, int out_size) {
    const float* x    = (const float*)d_in[0];
    const float* Wxh  = (const float*)d_in[1];
    const float* Whh  = (const float*)d_in[2];
    const float* bh   = (const float*)d_in[3];
    const float* Wout = (const float*)d_in[4];
    const float* bout = (const float*)d_in[5];
    float* out = (float*)d_out;

    cudaFuncSetAttribute(p1_kernel, cudaFuncAttributeMaxDynamicSharedMemorySize, P1_SMEM);
    cudaFuncSetAttribute(rnn_kernel, cudaFuncAttributeMaxDynamicSharedMemorySize, RNN_SMEM);
    cudaFuncSetAttribute(p3_kernel, cudaFuncAttributeMaxDynamicSharedMemorySize, P3_SMEM);

    p1_kernel<<<(B_ * T_ / 128) * 2, 256, P1_SMEM>>>(x, Wxh, bh);
    p3t_kernel<<<64, 256>>>(Wout);
    rnn_kernel<<<B_, 256, RNN_SMEM>>>(Whh);
    p3_kernel<<<B_ * T_ / 128, 256, P3_SMEM>>>(bout, out);
}

// round 13
// speedup vs baseline: 1.4109x; 1.0559x over previous
#include <cuda_runtime.h>

#define B_ 128
#define T_ 1024
#define I_ 128
#define H_ 256
#define O_ 64

// Scratch (device globals — no allocations allowed)
__device__ float g_xw[(size_t)B_ * T_ * H_];  // 128 MB: x @ W_xh^T + b_h
__device__ float g_hs[(size_t)B_ * T_ * H_];  // 128 MB: hidden states

// ---------------------------------------------------------------------------
// Packed f32x2 helpers (sm_103a FFMA2 path)
// ---------------------------------------------------------------------------
__device__ __forceinline__ void ffma2(unsigned long long &acc,
                                      unsigned long long a,
                                      unsigned long long b) {
    asm("fma.rn.f32x2 %0, %1, %2, %0;" : "+l"(acc) : "l"(a), "l"(b));
}
__device__ __forceinline__ unsigned long long dup2(float a) {
    unsigned long long r;
    asm("mov.b64 %0, {%1, %1};" : "=l"(r) : "f"(a));
    return r;
}
__device__ __forceinline__ float2 unpack2(unsigned long long v) {
    float2 r;
    asm("mov.b64 {%0, %1}, %2;" : "=f"(r.x), "=f"(r.y) : "l"(v));
    return r;
}

// ---------------------------------------------------------------------------
// Phase 1: g_xw[row,h] = sum_i x[row,i] * W_xh[h,i] + b_h[h]
// NT GEMM: M=131072 rows, N=256, K=128. Tile 128x128, K chunked 2x64 so
// smem = 68.6KB -> 2 CTAs/SM (16 warps).  (R9 version, ~180us)
// ---------------------------------------------------------------------------
#define P1_APAD 68
#define P1_BPAD 132
#define P1_SMEM ((128 * P1_APAD + 64 * P1_BPAD) * 4)

__global__ __launch_bounds__(256, 2) void p1_kernel(
    const float* __restrict__ x, const float* __restrict__ Wxh,
    const float* __restrict__ bh) {
    extern __shared__ float sm[];
    float* As  = sm;                  // [128 m][P1_APAD] (m x k-chunk)
    float* BsT = sm + 128 * P1_APAD;  // [64 k][P1_BPAD]  (k x n)
    const int tid = threadIdx.x;
    const int mt = blockIdx.x >> 1;
    const int nt = blockIdx.x & 1;
    const int tx = tid & 15, ty = tid >> 4;

    unsigned long long acc[8][4];
#pragma unroll
    for (int u = 0; u < 8; u++)
#pragma unroll
        for (int v = 0; v < 4; v++) acc[u][v] = 0ull;

    const int n = tid & 127, kh = tid >> 7;  // B-loader mapping

    for (int kc = 0; kc < 2; kc++) {
        if (kc) __syncthreads();
        const float* Ag = x + (size_t)mt * 128 * I_ + kc * 64;
#pragma unroll
        for (int i = 0; i < 8; i++) {
            int lin = tid + 256 * i;
            int r = lin >> 4, c4 = lin & 15;
            float4 v = ((const float4*)(Ag + r * I_))[c4];
            *(float4*)(As + r * P1_APAD + c4 * 4) = v;
        }
        {
            const float4* Bg = (const float4*)(Wxh + (size_t)(nt * 128 + n) * I_ +
                                               kc * 64 + kh * 32);
#pragma unroll
            for (int q = 0; q < 8; q++) {
                float4 v = Bg[q];
                int kb = kh * 32 + q * 4;
                BsT[(kb + 0) * P1_BPAD + n] = v.x;
                BsT[(kb + 1) * P1_BPAD + n] = v.y;
                BsT[(kb + 2) * P1_BPAD + n] = v.z;
                BsT[(kb + 3) * P1_BPAD + n] = v.w;
            }
        }
        __syncthreads();

#pragma unroll 2
        for (int k = 0; k < 64; k++) {
            unsigned long long a2[8], b2[4];
#pragma unroll
            for (int u = 0; u < 8; u++)
                a2[u] = dup2(As[(ty + 16 * u) * P1_APAD + k]);
#pragma unroll
            for (int v = 0; v < 4; v++)
                b2[v] = *(const unsigned long long*)(BsT + k * P1_BPAD + 2 * tx + 32 * v);
#pragma unroll
            for (int u = 0; u < 8; u++)
#pragma unroll
                for (int v = 0; v < 4; v++) ffma2(acc[u][v], a2[u], b2[v]);
        }
    }

    float2 bias[4];
#pragma unroll
    for (int v = 0; v < 4; v++)
        bias[v] = *(const float2*)(bh + nt * 128 + 2 * tx + 32 * v);
#pragma unroll
    for (int u = 0; u < 8; u++) {
        size_t row = (size_t)mt * 128 + ty + 16 * u;
        float* op = g_xw + row * H_ + nt * 128;
#pragma unroll
        for (int v = 0; v < 4; v++) {
            float2 r = unpack2(acc[u][v]);
            r.x += bias[v].x;
            r.y += bias[v].y;
            *(float2*)(op + 2 * tx + 32 * v) = r;
        }
    }
}

// ---------------------------------------------------------------------------
// Phase 2: sequential scan. 1 CTA per batch (128 CTAs), 256 threads.
// Thread h computes h_new[h]. W row h: k-chunks 0..45 in regs (92 u64),
// chunks 46..63 in smem as ulonglong2 [j2][h]. 4-deep h-prefetch ring
// (distance 4 ~= LDS latency), 2-deep W-prefetch ring, 4 acc chains,
// 4-deep xW register FIFO.
// ---------------------------------------------------------------------------
#define NJR 92   // u64 W pairs in registers: chunks j = 0..45
#define NJS2 18  // ulonglong2 W chunks in smem: j = 46..63
#define RNN_SMEM (NJS2 * H_ * 16 + 2 * H_ * 4)
#define XF 4

__global__ __launch_bounds__(256, 1) void rnn_kernel(
    const float* __restrict__ Whh) {
    extern __shared__ char smraw[];
    ulonglong2* Wsm2 = (ulonglong2*)smraw;          // [NJS2][H_]
    float* hb = (float*)(smraw + NJS2 * H_ * 16);   // [2][H_]
    const int h = threadIdx.x;
    const int b = blockIdx.x;

    const unsigned long long* wrow =
        (const unsigned long long*)(Whh + (size_t)h * H_);
    unsigned long long wreg[NJR];
#pragma unroll
    for (int j = 0; j < NJR; j++) wreg[j] = wrow[j];
#pragma unroll
    for (int j2 = 0; j2 < NJS2; j2++) {
        ulonglong2 wv;
        wv.x = wrow[NJR + 2 * j2];
        wv.y = wrow[NJR + 2 * j2 + 1];
        Wsm2[j2 * H_ + h] = wv;
    }
    hb[h] = 0.0f;
    hb[H_ + h] = 0.0f;

    const float* xwp = g_xw + (size_t)b * T_ * H_ + h;
    float* hsp = g_hs + (size_t)b * T_ * H_ + h;

    float xwf[XF];
#pragma unroll
    for (int i = 0; i < XF; i++)
        xwf[i] = __ldg(xwp + (size_t)i * H_);
    __syncthreads();

    int cur = 0;
#pragma unroll 1
    for (int t = 0; t < T_; t++) {
        const ulonglong2* h2 = (const ulonglong2*)(hb + cur * H_);
        unsigned long long acc0 = 0ull, acc1 = 0ull, acc2 = 0ull, acc3 = 0ull;

        // warm the prefetch rings
        ulonglong2 hring[4];
#pragma unroll
        for (int i = 0; i < 4; i++) hring[i] = h2[i];
        ulonglong2 wring[2];
        wring[0] = Wsm2[0 * H_ + h];
        wring[1] = Wsm2[1 * H_ + h];

        // register-W part: chunks 0..45
#pragma unroll
        for (int j = 0; j < NJR / 2; j++) {
            ulonglong2 hv = hring[j & 3];
            hring[j & 3] = h2[j + 4];  // j+4 <= 49 < 64: safe
            if (j & 1) {
                ffma2(acc2, hv.x, wreg[2 * j]);
                ffma2(acc3, hv.y, wreg[2 * j + 1]);
            } else {
                ffma2(acc0, hv.x, wreg[2 * j]);
                ffma2(acc1, hv.y, wreg[2 * j + 1]);
            }
        }
        // smem-W part: chunks 46..63
#pragma unroll
        for (int j2 = 0; j2 < NJS2; j2++) {
            const int j = NJR / 2 + j2;
            ulonglong2 hv = hring[j & 3];
            if (j + 4 < 64) hring[j & 3] = h2[j + 4];
            ulonglong2 wv = wring[j2 & 1];
            if (j2 + 2 < NJS2) wring[j2 & 1] = Wsm2[(j2 + 2) * H_ + h];
            if (j & 1) {
                ffma2(acc2, hv.x, wv.x);
                ffma2(acc3, hv.y, wv.y);
            } else {
                ffma2(acc0, hv.x, wv.x);
                ffma2(acc1, hv.y, wv.y);
            }
        }

        float2 a0 = unpack2(acc0), a1 = unpack2(acc1);
        float2 a2 = unpack2(acc2), a3 = unpack2(acc3);
        float s = ((a0.x + a0.y) + (a1.x + a1.y)) +
                  ((a2.x + a2.y) + (a3.x + a3.y));
        float hnew = fmaxf(xwf[t & (XF - 1)] + s, 0.0f);
        hb[(cur ^ 1) * H_ + h] = hnew;
        hsp[(size_t)t * H_] = hnew;
        xwf[t & (XF - 1)] = __ldg(xwp + (size_t)((t + XF) & (T_ - 1)) * H_);
        cur ^= 1;
        __syncthreads();
    }
}

// ---------------------------------------------------------------------------
// Phase 3: out[row,o] = sum_h g_hs[row,h] * W_out[o,h] + b_out[o]
// M=131072, N=64, K=256. Tile 128 rows x 64 cols. (R4 version, ~90us)
// ---------------------------------------------------------------------------
#define P3_WPAD 66
#define P3_APAD 68
#define P3_SMEM ((256 * P3_WPAD + 128 * P3_APAD) * 4)

__global__ __launch_bounds__(256, 1) void p3_kernel(
    const float* __restrict__ Wout, const float* __restrict__ bout,
    float* __restrict__ out) {
    extern __shared__ float sm[];
    float* WsT = sm;                    // [256 k][P3_WPAD] (k x o)
    float* As  = sm + 256 * P3_WPAD;    // [128 m][P3_APAD] (m x k-chunk)
    const int tid = threadIdx.x;
    const int mt = blockIdx.x;

    {
        int o = tid >> 2, kq = tid & 3;
        const float4* Wg = (const float4*)(Wout + (size_t)o * H_ + kq * 64);
#pragma unroll
        for (int q = 0; q < 16; q++) {
            float4 v = Wg[q];
            int kb = kq * 64 + q * 4;
            WsT[(kb + 0) * P3_WPAD + o] = v.x;
            WsT[(kb + 1) * P3_WPAD + o] = v.y;
            WsT[(kb + 2) * P3_WPAD + o] = v.z;
            WsT[(kb + 3) * P3_WPAD + o] = v.w;
        }
    }

    const int tx = tid & 15, ty = tid >> 4;
    unsigned long long acc[8][2];
#pragma unroll
    for (int u = 0; u < 8; u++) { acc[u][0] = 0ull; acc[u][1] = 0ull; }

    for (int kc = 0; kc < 4; kc++) {
        __syncthreads();
#pragma unroll
        for (int i = 0; i < 8; i++) {
            int lin = tid + 256 * i;
            int r = lin >> 4, c4 = lin & 15;
            float4 v = *(const float4*)(g_hs + ((size_t)mt * 128 + r) * H_ +
                                        kc * 64 + c4 * 4);
            *(float4*)(As + r * P3_APAD + c4 * 4) = v;
        }
        __syncthreads();
#pragma unroll 4
        for (int k = 0; k < 64; k++) {
            unsigned long long b0 = *(const unsigned long long*)(
                WsT + (kc * 64 + k) * P3_WPAD + 2 * tx);
            unsigned long long b1 = *(const unsigned long long*)(
                WsT + (kc * 64 + k) * P3_WPAD + 2 * tx + 32);
#pragma unroll
            for (int u = 0; u < 8; u++) {
                unsigned long long a2 = dup2(As[(ty + 16 * u) * P3_APAD + k]);
                ffma2(acc[u][0], a2, b0);
                ffma2(acc[u][1], a2, b1);
            }
        }
    }

    float2 bias0 = *(const float2*)(bout + 2 * tx);
    float2 bias1 = *(const float2*)(bout + 2 * tx + 32);
#pragma unroll
    for (int u = 0; u < 8; u++) {
        size_t row = (size_t)mt * 128 + ty + 16 * u;
        float2 r0 = unpack2(acc[u][0]);
        float2 r1 = unpack2(acc[u][1]);
        r0.x += bias0.x; r0.y += bias0.y;
        r1.x += bias1.x; r1.y += bias1.y;
        *(float2*)(out + row * O_ + 2 * tx) = r0;
        *(float2*)(out + row * O_ + 2 * tx + 32) = r1;
    }
}

// ---------------------------------------------------------------------------
extern "C" void kernel_launch(void* const* d_in, const int* in_sizes, int n_in,
                              void* d_out, int out_size) {
    const float* x    = (const float*)d_in[0];
    const float* Wxh  = (const float*)d_in[1];
    const float* Whh  = (const float*)d_in[2];
    const float* bh   = (const float*)d_in[3];
    const float* Wout = (const float*)d_in[4];
    const float* bout = (const float*)d_in[5];
    float* out = (float*)d_out;

    cudaFuncSetAttribute(p1_kernel, cudaFuncAttributeMaxDynamicSharedMemorySize, P1_SMEM);
    cudaFuncSetAttribute(rnn_kernel, cudaFuncAttributeMaxDynamicSharedMemorySize, RNN_SMEM);
    cudaFuncSetAttribute(p3_kernel, cudaFuncAttributeMaxDynamicSharedMemorySize, P3_SMEM);

    p1_kernel<<<(B_ * T_ / 128) * 2, 256, P1_SMEM>>>(x, Wxh, bh);
    rnn_kernel<<<B_, 256, RNN_SMEM>>>(Whh);
    p3_kernel<<<B_ * T_ / 128, 256, P3_SMEM>>>(Wout, bout, out);
}